// round 3
// baseline (speedup 1.0000x reference)
#include <cuda_runtime.h>
#include <math.h>

#define B 8
#define CIN 512
#define COUT 128
#define HW16 256   // 16x16
#define HW 196     // 14x14
#define CC 16384   // 128*128

// Scratch (device globals -- no allocation allowed)
__device__ float g_y[B * COUT * HW16];                 // 262144 floats
__device__ float g_A[B * COUT * HW];                   // 200704 floats
__device__ float g_R[(size_t)B * COUT * COUT * HW];    // 25,690,112 floats (~98 MB)
__device__ float g_cij[B * CC];                        // 131072 floats

// ---------------------------------------------------------------------------
// Kernel 1: 1x1 conv (GEMM) + ReLU.  Y[b,o,p] = relu(sum_i W[o,i] * X[b,i,p])
// grid (B, 8 o-tiles of 16), block 256 (thread = spatial position p)
// ---------------------------------------------------------------------------
__global__ void k_gemm_relu(const float* __restrict__ x, const float* __restrict__ w) {
    int b = blockIdx.x;
    int ot = blockIdx.y;
    int p = threadIdx.x;

    __shared__ float Wsm[16][CIN];
    for (int idx = threadIdx.x; idx < 16 * CIN; idx += 256) {
        int r = idx >> 9;
        int i = idx & (CIN - 1);
        Wsm[r][i] = w[(ot * 16 + r) * CIN + i];
    }
    __syncthreads();

    float acc[16];
#pragma unroll
    for (int r = 0; r < 16; ++r) acc[r] = 0.f;

    const float* xb = x + (size_t)b * CIN * HW16 + p;
    for (int i = 0; i < CIN; ++i) {
        float xv = xb[(size_t)i * HW16];
#pragma unroll
        for (int r = 0; r < 16; ++r) acc[r] = fmaf(Wsm[r][i], xv, acc[r]);
    }

    float* yb = g_y + ((size_t)b * COUT + ot * 16) * HW16 + p;
#pragma unroll
    for (int r = 0; r < 16; ++r) yb[(size_t)r * HW16] = fmaxf(acc[r], 0.f);
}

// ---------------------------------------------------------------------------
// Kernel 2: depthwise 3x3 Gaussian, VALID padding.  16x16 -> 14x14.
// ---------------------------------------------------------------------------
__global__ void k_dwconv() {
    int idx = blockIdx.x * 256 + threadIdx.x;
    if (idx >= B * COUT * HW) return;
    int p  = idx % HW;
    int bc = idx / HW;
    int ow = p % 14;
    int oh = p / 14;
    const float* yb = g_y + (size_t)bc * HW16;

    const float W0 = 0.63661977236758134308f;   // 1/(2*pi*0.25)
    const float W1 = W0 * expf(-2.0f);
    const float W2 = W0 * expf(-4.0f);

#define Yv(r, cl) yb[(oh + (r)) * 16 + (ow + (cl))]
    float s = W2 * (Yv(0,0) + Yv(0,2) + Yv(2,0) + Yv(2,2))
            + W1 * (Yv(0,1) + Yv(1,0) + Yv(1,2) + Yv(2,1))
            + W0 *  Yv(1,1);
#undef Yv
    g_A[idx] = s;
}

// ---------------------------------------------------------------------------
// Kernel 3: circular convolution for all channel pairs.
//   R[b,a,c,p] = sum_j A[b,c,j] * A[b,a,(p-j) mod 196]
// grid (a=128, b=8), block 196 threads = 49 p-groups x 4 c-groups.
// Thread: 4 consecutive p, 32 c's (2 at a time).  A tile + duplicated a-row
// live in dynamic shared memory (~102 KB).
// ---------------------------------------------------------------------------
__global__ void __launch_bounds__(196) k_corr() {
    extern __shared__ float sm[];
    float* Asm = sm;                // [128*196]
    float* fa2 = sm + COUT * HW;    // [392] : a-row duplicated (kills the mod)

    int a = blockIdx.x;
    int b = blockIdx.y;
    const float* Ab = g_A + (size_t)b * COUT * HW;

    for (int i = threadIdx.x; i < COUT * HW; i += 196) Asm[i] = Ab[i];
    const float* fa = Ab + a * HW;
    for (int i = threadIdx.x; i < 2 * HW; i += 196) fa2[i] = fa[i >= HW ? i - HW : i];
    __syncthreads();

    int pg = threadIdx.x % 49;
    int cg = threadIdx.x / 49;
    int p0 = pg * 4;

    float* Rb = g_R + ((size_t)(b * COUT + a)) * (COUT * HW);
    const float* fw = fa2 + p0 + HW;   // fw[k - j] = A[a, (p0+k-j) mod 196]

    for (int cc = 0; cc < 32; cc += 2) {
        int c0 = cg * 32 + cc;
        const float* fc0 = Asm + c0 * HW;
        const float* fc1 = fc0 + HW;

        float a00 = 0.f, a01 = 0.f, a02 = 0.f, a03 = 0.f;
        float a10 = 0.f, a11 = 0.f, a12 = 0.f, a13 = 0.f;

#pragma unroll 4
        for (int j = 0; j < HW; ++j) {
            float v0 = fw[0 - j];
            float v1 = fw[1 - j];
            float v2 = fw[2 - j];
            float v3 = fw[3 - j];
            float b0 = fc0[j];
            float b1 = fc1[j];
            a00 = fmaf(v0, b0, a00); a01 = fmaf(v1, b0, a01);
            a02 = fmaf(v2, b0, a02); a03 = fmaf(v3, b0, a03);
            a10 = fmaf(v0, b1, a10); a11 = fmaf(v1, b1, a11);
            a12 = fmaf(v2, b1, a12); a13 = fmaf(v3, b1, a13);
        }

        *reinterpret_cast<float4*>(Rb + c0 * HW + p0)       = make_float4(a00, a01, a02, a03);
        *reinterpret_cast<float4*>(Rb + (c0 + 1) * HW + p0) = make_float4(a10, a11, a12, a13);
    }
}

// ---------------------------------------------------------------------------
// Kernel 4: out[b,v] = sqrt(max_u R_flat[b, u*16384 + v]),  u in [0,196).
// Flat (a,c,p) order of g_R makes this a coalesced strided gather.
// ---------------------------------------------------------------------------
__global__ void k_maxred() {
    int idx = blockIdx.x * 256 + threadIdx.x;   // < 131072
    int b = idx >> 14;
    int v = idx & (CC - 1);
    const float* Rb = g_R + (size_t)b * (COUT * COUT * HW) + v;
    float m = 0.f;   // R >= 0 always (relu + nonneg gaussian)
#pragma unroll 4
    for (int u = 0; u < HW; ++u) m = fmaxf(m, Rb[(size_t)u * CC]);
    g_cij[idx] = sqrtf(m);
}

// ---------------------------------------------------------------------------
// Kernel 5: per-batch normalize: out = c_ij / (sum(c_ij^2) + EPS)
// ---------------------------------------------------------------------------
__global__ void k_norm(float* __restrict__ out) {
    int b = blockIdx.x;
    __shared__ float red[256];
    const float* cb = g_cij + b * CC;

    float s = 0.f;
    for (int v = threadIdx.x; v < CC; v += 256) {
        float c = cb[v];
        s += c * c;
    }
    red[threadIdx.x] = s;
    __syncthreads();
    for (int st = 128; st > 0; st >>= 1) {
        if (threadIdx.x < st) red[threadIdx.x] += red[threadIdx.x + st];
        __syncthreads();
    }
    float inv = 1.0f / (red[0] + 1e-11f);

    float* ob = out + b * CC;
    for (int v = threadIdx.x; v < CC; v += 256) ob[v] = cb[v] * inv;
}

// ---------------------------------------------------------------------------
extern "C" void kernel_launch(void* const* d_in, const int* in_sizes, int n_in,
                              void* d_out, int out_size) {
    const float* x = (const float*)d_in[0];   // (8, 512, 16, 16)
    const float* w = (const float*)d_in[1];   // (128, 512)
    float* out = (float*)d_out;               // (8, 16384)

    const int smem3 = (COUT * HW + 2 * HW) * (int)sizeof(float);  // 101,920 B
    cudaFuncSetAttribute(k_corr, cudaFuncAttributeMaxDynamicSharedMemorySize, smem3);

    k_gemm_relu<<<dim3(B, 8), 256>>>(x, w);
    k_dwconv<<<(B * COUT * HW + 255) / 256, 256>>>();
    k_corr<<<dim3(COUT, B), 196, smem3>>>();
    k_maxred<<<(B * CC) / 256, 256>>>();
    k_norm<<<B, 256>>>(out);
}

// round 4
// speedup vs baseline: 1.0990x; 1.0990x over previous
#include <cuda_runtime.h>
#include <math.h>

#define B 8
#define CIN 512
#define COUT 128
#define HW16 256   // 16x16
#define HW 196     // 14x14
#define CC 16384   // 128*128

// Scratch (device globals -- no allocation allowed)
__device__ float g_y[B * COUT * HW16];                 // 262144 floats
__device__ float g_A[B * COUT * HW];                   // 200704 floats
__device__ float g_R[(size_t)B * COUT * COUT * HW];    // 25,690,112 floats (~98 MB)
__device__ float g_cij[B * CC];                        // 131072 floats

// ---------------------------------------------------------------------------
// Kernel 1: 1x1 conv (GEMM) + ReLU.  Y[b,o,p] = relu(sum_i W[o,i] * X[b,i,p])
// grid (B, 8 o-tiles of 16), block 256 (thread = spatial position p)
// ---------------------------------------------------------------------------
__global__ void k_gemm_relu(const float* __restrict__ x, const float* __restrict__ w) {
    int b = blockIdx.x;
    int ot = blockIdx.y;
    int p = threadIdx.x;

    __shared__ float Wsm[16][CIN];
    for (int idx = threadIdx.x; idx < 16 * CIN; idx += 256) {
        int r = idx >> 9;
        int i = idx & (CIN - 1);
        Wsm[r][i] = w[(ot * 16 + r) * CIN + i];
    }
    __syncthreads();

    float acc[16];
#pragma unroll
    for (int r = 0; r < 16; ++r) acc[r] = 0.f;

    const float* xb = x + (size_t)b * CIN * HW16 + p;
    for (int i = 0; i < CIN; ++i) {
        float xv = xb[(size_t)i * HW16];
#pragma unroll
        for (int r = 0; r < 16; ++r) acc[r] = fmaf(Wsm[r][i], xv, acc[r]);
    }

    float* yb = g_y + ((size_t)b * COUT + ot * 16) * HW16 + p;
#pragma unroll
    for (int r = 0; r < 16; ++r) yb[(size_t)r * HW16] = fmaxf(acc[r], 0.f);
}

// ---------------------------------------------------------------------------
// Kernel 2: depthwise 3x3 Gaussian, VALID padding.  16x16 -> 14x14.
// ---------------------------------------------------------------------------
__global__ void k_dwconv() {
    int idx = blockIdx.x * 256 + threadIdx.x;
    if (idx >= B * COUT * HW) return;
    int p  = idx % HW;
    int bc = idx / HW;
    int ow = p % 14;
    int oh = p / 14;
    const float* yb = g_y + (size_t)bc * HW16;

    const float W0 = 0.63661977236758134308f;   // 1/(2*pi*0.25)
    const float W1 = W0 * expf(-2.0f);
    const float W2 = W0 * expf(-4.0f);

#define Yv(r, cl) yb[(oh + (r)) * 16 + (ow + (cl))]
    float s = W2 * (Yv(0,0) + Yv(0,2) + Yv(2,0) + Yv(2,2))
            + W1 * (Yv(0,1) + Yv(1,0) + Yv(1,2) + Yv(2,1))
            + W0 *  Yv(1,1);
#undef Yv
    g_A[idx] = s;
}

// ---------------------------------------------------------------------------
// Kernel 3: circular convolution for all channel pairs.
//   R[b,a,c,p] = sum_j A[b,c,j] * A[b,a,(p-j) mod 196]
// grid (a=128, b=8), block 196 threads = 49 p-groups x 4 c-groups.
// Thread: 4 consecutive p, 32 c's (2 at a time).  A tile + duplicated a-row
// live in dynamic shared memory (~102 KB).
// ---------------------------------------------------------------------------
__global__ void __launch_bounds__(196) k_corr() {
    extern __shared__ float sm[];
    float* Asm = sm;                // [128*196]
    float* fa2 = sm + COUT * HW;    // [392] : a-row duplicated (kills the mod)

    int a = blockIdx.x;
    int b = blockIdx.y;
    const float* Ab = g_A + (size_t)b * COUT * HW;

    for (int i = threadIdx.x; i < COUT * HW; i += 196) Asm[i] = Ab[i];
    const float* fa = Ab + a * HW;
    for (int i = threadIdx.x; i < 2 * HW; i += 196) fa2[i] = fa[i >= HW ? i - HW : i];
    __syncthreads();

    int pg = threadIdx.x % 49;
    int cg = threadIdx.x / 49;
    int p0 = pg * 4;

    float* Rb = g_R + ((size_t)(b * COUT + a)) * (COUT * HW);
    const float* fw = fa2 + p0 + HW;   // fw[k - j] = A[a, (p0+k-j) mod 196]

    for (int cc = 0; cc < 32; cc += 2) {
        int c0 = cg * 32 + cc;
        const float* fc0 = Asm + c0 * HW;
        const float* fc1 = fc0 + HW;

        float a00 = 0.f, a01 = 0.f, a02 = 0.f, a03 = 0.f;
        float a10 = 0.f, a11 = 0.f, a12 = 0.f, a13 = 0.f;

#pragma unroll 4
        for (int j = 0; j < HW; ++j) {
            float v0 = fw[0 - j];
            float v1 = fw[1 - j];
            float v2 = fw[2 - j];
            float v3 = fw[3 - j];
            float b0 = fc0[j];
            float b1 = fc1[j];
            a00 = fmaf(v0, b0, a00); a01 = fmaf(v1, b0, a01);
            a02 = fmaf(v2, b0, a02); a03 = fmaf(v3, b0, a03);
            a10 = fmaf(v0, b1, a10); a11 = fmaf(v1, b1, a11);
            a12 = fmaf(v2, b1, a12); a13 = fmaf(v3, b1, a13);
        }

        *reinterpret_cast<float4*>(Rb + c0 * HW + p0)       = make_float4(a00, a01, a02, a03);
        *reinterpret_cast<float4*>(Rb + (c0 + 1) * HW + p0) = make_float4(a10, a11, a12, a13);
    }
}

// ---------------------------------------------------------------------------
// Kernel 4: out[b,v] = sqrt(max_u R_flat[b, u*16384 + v]),  u in [0,196).
// Flat (a,c,p) order of g_R makes this a coalesced strided gather.
// ---------------------------------------------------------------------------
__global__ void k_maxred() {
    int idx = blockIdx.x * 256 + threadIdx.x;   // < 131072
    int b = idx >> 14;
    int v = idx & (CC - 1);
    const float* Rb = g_R + (size_t)b * (COUT * COUT * HW) + v;
    float m = 0.f;   // R >= 0 always (relu + nonneg gaussian)
#pragma unroll 4
    for (int u = 0; u < HW; ++u) m = fmaxf(m, Rb[(size_t)u * CC]);
    g_cij[idx] = sqrtf(m);
}

// ---------------------------------------------------------------------------
// Kernel 5: per-batch normalize: out = c_ij / (sum(c_ij^2) + EPS)
// ---------------------------------------------------------------------------
__global__ void k_norm(float* __restrict__ out) {
    int b = blockIdx.x;
    __shared__ float red[256];
    const float* cb = g_cij + b * CC;

    float s = 0.f;
    for (int v = threadIdx.x; v < CC; v += 256) {
        float c = cb[v];
        s += c * c;
    }
    red[threadIdx.x] = s;
    __syncthreads();
    for (int st = 128; st > 0; st >>= 1) {
        if (threadIdx.x < st) red[threadIdx.x] += red[threadIdx.x + st];
        __syncthreads();
    }
    float inv = 1.0f / (red[0] + 1e-11f);

    float* ob = out + b * CC;
    for (int v = threadIdx.x; v < CC; v += 256) ob[v] = cb[v] * inv;
}

// ---------------------------------------------------------------------------
extern "C" void kernel_launch(void* const* d_in, const int* in_sizes, int n_in,
                              void* d_out, int out_size) {
    const float* x = (const float*)d_in[0];   // (8, 512, 16, 16)
    const float* w = (const float*)d_in[1];   // (128, 512)
    float* out = (float*)d_out;               // (8, 16384)

    const int smem3 = (COUT * HW + 2 * HW) * (int)sizeof(float);  // 101,920 B
    cudaFuncSetAttribute(k_corr, cudaFuncAttributeMaxDynamicSharedMemorySize, smem3);

    k_gemm_relu<<<dim3(B, 8), 256>>>(x, w);
    k_dwconv<<<(B * COUT * HW + 255) / 256, 256>>>();
    k_corr<<<dim3(COUT, B), 196, smem3>>>();
    k_maxred<<<(B * CC) / 256, 256>>>();
    k_norm<<<B, 256>>>(out);
}